// round 10
// baseline (speedup 1.0000x reference)
#include <cuda_runtime.h>
#include <cstdint>

#define BH 16
#define NS 256
#define DH 64
#define EPSF 1.1920929e-07f

// ---------------- scratch (device globals; no allocs) ----------------
__device__ __align__(16) float g_qkv[512 * 2560];
__device__ __align__(16) float g_qn [BH * NS * DH];
__device__ __align__(16) float g_k1 [BH * NS * DH];
__device__ __align__(16) float g_k2 [BH * NS * DH];
__device__ __align__(16) float g_v1t[BH * DH * NS];
__device__ __align__(16) float g_v2t[BH * DH * NS];
__device__ __align__(16) float g_e1 [BH * NS * NS];
__device__ __align__(16) float g_e2 [BH * NS * NS];
__device__ __align__(16) float g_e3 [BH * NS * NS];
__device__ __align__(16) float g_numP[4][BH * NS * DH];
__device__ __align__(16) float g_denP[4][BH * NS];
__device__ __align__(16) float g_o  [512 * 512];

__device__ __forceinline__ uint32_t cvt_tf32(float x) {
    uint32_t r; asm("cvt.rna.tf32.f32 %0, %1;" : "=r"(r) : "f"(x)); return r;
}
__device__ __forceinline__ uint32_t smem_u32(const void* p) {
    uint32_t a;
    asm("{ .reg .u64 t; cvta.to.shared.u64 t, %1; cvt.u32.u64 %0, t; }" : "=r"(a) : "l"(p));
    return a;
}
__device__ __forceinline__ void mma_tf32(float* c,
        uint32_t a0, uint32_t a1, uint32_t a2, uint32_t a3,
        uint32_t b0, uint32_t b1) {
    asm volatile("mma.sync.aligned.m16n8k8.row.col.f32.tf32.tf32.f32 "
        "{%0,%1,%2,%3}, {%4,%5,%6,%7}, {%8,%9}, {%0,%1,%2,%3};"
        : "+f"(c[0]), "+f"(c[1]), "+f"(c[2]), "+f"(c[3])
        : "r"(a0), "r"(a1), "r"(a2), "r"(a3), "r"(b0), "r"(b1));
}
__device__ __forceinline__ void ldsm_x4(uint32_t& r0, uint32_t& r1,
                                        uint32_t& r2, uint32_t& r3, uint32_t a) {
    asm volatile("ldmatrix.sync.aligned.m8n8.x4.shared.b16 {%0,%1,%2,%3}, [%4];"
                 : "=r"(r0), "=r"(r1), "=r"(r2), "=r"(r3) : "r"(a));
}

// ---------------- generic SGEMM: C[M,N] = A[M,K] @ B[K,N] ----------------
__global__ void sgemm128x64(const float* __restrict__ A, const float* __restrict__ B,
                            float* __restrict__ C, int M, int N, int K) {
    __shared__ float As[16][128];
    __shared__ float Bs[16][64];
    int t = threadIdx.x;
    int tx = t & 15, ty = t >> 4;
    int m0 = blockIdx.y * 128, n0 = blockIdx.x * 64;

    float acc[8][4];
#pragma unroll
    for (int i = 0; i < 8; i++)
#pragma unroll
        for (int j = 0; j < 4; j++) acc[i][j] = 0.f;

    for (int kt = 0; kt < K; kt += 16) {
#pragma unroll
        for (int q = 0; q < 2; q++) {
            int lin = t + q * 256;
            int m = lin & 127, kq = lin >> 7;
            float4 v = *(const float4*)&A[(size_t)(m0 + m) * K + kt + kq * 4];
            As[kq * 4 + 0][m] = v.x; As[kq * 4 + 1][m] = v.y;
            As[kq * 4 + 2][m] = v.z; As[kq * 4 + 3][m] = v.w;
        }
        {
            int kk = t >> 4, nq = t & 15;
            float4 v = *(const float4*)&B[(size_t)(kt + kk) * N + n0 + nq * 4];
            *(float4*)&Bs[kk][nq * 4] = v;
        }
        __syncthreads();
#pragma unroll
        for (int kk = 0; kk < 16; kk++) {
            float4 b = *(float4*)&Bs[kk][tx * 4];
            float a[8];
#pragma unroll
            for (int i = 0; i < 8; i++) a[i] = As[kk][ty * 8 + i];
#pragma unroll
            for (int i = 0; i < 8; i++) {
                acc[i][0] += a[i] * b.x; acc[i][1] += a[i] * b.y;
                acc[i][2] += a[i] * b.z; acc[i][3] += a[i] * b.w;
            }
        }
        __syncthreads();
    }
#pragma unroll
    for (int i = 0; i < 8; i++) {
        float4 v = make_float4(acc[i][0], acc[i][1], acc[i][2], acc[i][3]);
        *(float4*)&C[(size_t)(m0 + ty * 8 + i) * N + n0 + tx * 4] = v;
    }
}

// ---------------- split + rmsnorm + pack ----------------
__global__ void pack_norm(const float* __restrict__ qw,
                          const float* __restrict__ k1w,
                          const float* __restrict__ k2w) {
    int blk = blockIdx.x;
    int bh = blk >> 8, n = blk & 255;
    int b = bh >> 3, h = bh & 7;
    int dd = threadIdx.x;
    size_t base = (size_t)(b * 256 + n) * 2560 + h * 64 + dd;
    float q  = g_qkv[base];
    float k1 = g_qkv[base + 512];
    float k2 = g_qkv[base + 1024];
    float v1 = g_qkv[base + 1536];
    float v2 = g_qkv[base + 2048];

    __shared__ float sw[3][2];
    float sq = q * q, s1 = k1 * k1, s2 = k2 * k2;
#pragma unroll
    for (int o = 16; o; o >>= 1) {
        sq += __shfl_xor_sync(0xffffffffu, sq, o);
        s1 += __shfl_xor_sync(0xffffffffu, s1, o);
        s2 += __shfl_xor_sync(0xffffffffu, s2, o);
    }
    int w = dd >> 5;
    if ((dd & 31) == 0) { sw[0][w] = sq; sw[1][w] = s1; sw[2][w] = s2; }
    __syncthreads();
    float rq = rsqrtf((sw[0][0] + sw[0][1]) * (1.f / 64.f) + EPSF);
    float r1 = rsqrtf((sw[1][0] + sw[1][1]) * (1.f / 64.f) + EPSF);
    float r2 = rsqrtf((sw[2][0] + sw[2][1]) * (1.f / 64.f) + EPSF);

    int rb = bh * NS * DH + n * DH + dd;
    g_qn[rb] = q * rq * qw[dd] * 0.125f;
    g_k1[rb] = k1 * r1 * k1w[dd];
    g_k2[rb] = k2 * r2 * k2w[dd];
    g_v1t[bh * DH * NS + dd * NS + n] = v1;
    g_v2t[bh * DH * NS + dd * NS + n] = v2;
}

// ---------------- sims: e = exp(clip(scale * L @ R^T)) ----------------
__global__ void sims_kernel() {
    int z = blockIdx.z;
    int bh = z / 3, mat = z % 3;
    const float* L = ((mat == 2) ? g_k1 : g_qn) + bh * NS * DH;
    const float* R = ((mat == 0) ? g_k1 : g_k2) + bh * NS * DH;
    float* C = ((mat == 0) ? g_e1 : (mat == 1) ? g_e2 : g_e3) + (size_t)bh * NS * NS;
    float scale = (mat == 2) ? 0.125f : 1.f;

    __shared__ float As[16][128];
    __shared__ float Bs[16][64];
    int t = threadIdx.x, tx = t & 15, ty = t >> 4;
    int m0 = blockIdx.y * 128, n0 = blockIdx.x * 64;

    float acc[8][4];
#pragma unroll
    for (int i = 0; i < 8; i++)
#pragma unroll
        for (int j = 0; j < 4; j++) acc[i][j] = 0.f;

    for (int kt = 0; kt < 64; kt += 16) {
#pragma unroll
        for (int q = 0; q < 2; q++) {
            int lin = t + q * 256;
            int m = lin & 127, kq = lin >> 7;
            float4 v = *(const float4*)&L[(m0 + m) * 64 + kt + kq * 4];
            As[kq * 4 + 0][m] = v.x; As[kq * 4 + 1][m] = v.y;
            As[kq * 4 + 2][m] = v.z; As[kq * 4 + 3][m] = v.w;
        }
        {
            int n = t & 63, kq = t >> 6;
            float4 v = *(const float4*)&R[(n0 + n) * 64 + kt + kq * 4];
            Bs[kq * 4 + 0][n] = v.x; Bs[kq * 4 + 1][n] = v.y;
            Bs[kq * 4 + 2][n] = v.z; Bs[kq * 4 + 3][n] = v.w;
        }
        __syncthreads();
#pragma unroll
        for (int kk = 0; kk < 16; kk++) {
            float4 b = *(float4*)&Bs[kk][tx * 4];
            float a[8];
#pragma unroll
            for (int i = 0; i < 8; i++) a[i] = As[kk][ty * 8 + i];
#pragma unroll
            for (int i = 0; i < 8; i++) {
                acc[i][0] += a[i] * b.x; acc[i][1] += a[i] * b.y;
                acc[i][2] += a[i] * b.z; acc[i][3] += a[i] * b.w;
            }
        }
        __syncthreads();
    }
#pragma unroll
    for (int i = 0; i < 8; i++) {
        float4 v;
        v.x = __expf(fminf(40.f, fmaxf(-40.f, acc[i][0] * scale)));
        v.y = __expf(fminf(40.f, fmaxf(-40.f, acc[i][1] * scale)));
        v.z = __expf(fminf(40.f, fmaxf(-40.f, acc[i][2] * scale)));
        v.w = __expf(fminf(40.f, fmaxf(-40.f, acc[i][3] * scale)));
        *(float4*)&C[(size_t)(m0 + ty * 8 + i) * NS + n0 + tx * 4] = v;
    }
}

// ---------------- heavy: mma.sync tf32 + ldmatrix ----------------
// CTA (dg, ih, jh, bh): tile 128(i) x 64(j), 13 channels d.
//   G[i,j] = sum_k (e2[i,k]*v2[k,d]) * e3[j,k]   (m16n8k8 tf32, ldmatrix frags)
//   partial[i] = sum_j e1[i,j]*v1[j,d]*G[i,j]    (e1 frags held in regs across channels)
// smem: A tf32 (128x260) + e3 tf32 (64x260). e2/e1 stream from L2.
#define PCH 260
#define AS_OFF 0
#define E3_OFF 133120
#define V2_OFF 199680
#define V1_OFF 200704
#define RED_OFF 200960
#define SMEM_SZ 201984

__global__ void __launch_bounds__(256, 1) heavy_mma() {
    extern __shared__ __align__(16) char smem[];
    const uint32_t sb = smem_u32(smem);
    uint32_t* Asu = (uint32_t*)(smem + AS_OFF);
    uint32_t* E3u = (uint32_t*)(smem + E3_OFF);
    float*    v2s = (float*)(smem + V2_OFF);
    float*    v1s = (float*)(smem + V1_OFF);
    float*    red = (float*)(smem + RED_OFF);

    int t = threadIdx.x, lane = t & 31, wid = t >> 5;
    int wi = wid >> 1, wj = wid & 1;            // warp grid 4(i) x 2(j), tile 32x32
    int dg = blockIdx.x;                        // 0..4, 13 channels each
    int ih = blockIdx.y >> 2, jh = blockIdx.y & 3;
    int bh = blockIdx.z;

    const float* e2p = g_e2 + (size_t)bh * 65536 + (size_t)(ih * 128) * 256;
    const float* e3p = g_e3 + (size_t)bh * 65536 + (size_t)(jh * 64) * 256;
    const float* e1p = g_e1 + (size_t)bh * 65536 + (size_t)(ih * 128) * 256 + jh * 64;

    // ---- CTA-start: e3 -> smem tf32 ----
    for (int idx = t; idx < 4096; idx += 256) {     // 64 rows x 64 float4
        int r = idx >> 6, q = (idx & 63) << 2;
        float4 b = *(const float4*)&e3p[r * 256 + q];
        uint4 u;
        u.x = cvt_tf32(b.x); u.y = cvt_tf32(b.y);
        u.z = cvt_tf32(b.z); u.w = cvt_tf32(b.w);
        *(uint4*)&E3u[r * PCH + q] = u;
    }

    // ---- e1 fragments preloaded to registers (d-independent) ----
    float er[2][4][4];
#pragma unroll
    for (int mt = 0; mt < 2; mt++) {
        int i0 = wi * 32 + mt * 16 + (lane >> 2);
#pragma unroll
        for (int nt = 0; nt < 4; nt++) {
            int j = wj * 32 + nt * 8 + (lane & 3) * 2;
            float2 w0 = *(const float2*)&e1p[(size_t)i0 * 256 + j];
            float2 w1 = *(const float2*)&e1p[(size_t)(i0 + 8) * 256 + j];
            er[mt][nt][0] = w0.x; er[mt][nt][1] = w0.y;
            er[mt][nt][2] = w1.x; er[mt][nt][3] = w1.y;
        }
    }

    // ---- ldmatrix lane addresses ----
    int lr = lane & 7;
    uint32_t aRow = (uint32_t)(wi * 32 + ((lane >> 3) & 1) * 8 + lr);
    uint32_t aK   = (uint32_t)((lane >> 4) * 4);
    uint32_t aAddr0 = sb + AS_OFF + (aRow * PCH + aK) * 4;        // mt=0
    uint32_t aAddr1 = aAddr0 + 16 * PCH * 4;                       // mt=1
    uint32_t bRow = (uint32_t)(wj * 32 + ((lane >> 4) & 1) * 8 + lr);
    uint32_t bK   = (uint32_t)(((lane >> 3) & 1) * 4);
    uint32_t bAddr0 = sb + E3_OFF + (bRow * PCH + bK) * 4;         // nt 0,1
    uint32_t bAddr1 = bAddr0 + 16 * PCH * 4;                       // nt 2,3

    // A-build assignment: row = t>>1 (0..127), k-half = (t&1)*128
    int brow = t >> 1, bkb = (t & 1) << 7;
    const float* e2row = e2p + (size_t)brow * 256 + bkb;
    uint32_t*    asrow = Asu + brow * PCH + bkb;

    for (int ci = 0; ci < 13; ci++) {
        int d = dg * 13 + ci;
        if (t < 64)  v1s[t] = (d < 64) ? g_v1t[((size_t)bh * DH + d) * NS + jh * 64 + t] : 1.f;
        v2s[t] = (d < 64) ? g_v2t[((size_t)bh * DH + d) * NS + t] : 1.f;
        __syncthreads();

        // build A = tf32(e2 * v2_d), streamed from L2
#pragma unroll
        for (int q = 0; q < 32; q++) {
            float4 a = *(const float4*)(e2row + q * 4);
            float4 w = *(const float4*)&v2s[bkb + q * 4];
            uint4 u;
            u.x = cvt_tf32(a.x * w.x); u.y = cvt_tf32(a.y * w.y);
            u.z = cvt_tf32(a.z * w.z); u.w = cvt_tf32(a.w * w.w);
            *(uint4*)(asrow + q * 4) = u;
        }
        __syncthreads();

        // ---- MMA mainloop: 32 k-steps of 8 ----
        float acc[2][4][4];
#pragma unroll
        for (int m = 0; m < 2; m++)
#pragma unroll
            for (int n = 0; n < 4; n++)
#pragma unroll
                for (int c = 0; c < 4; c++) acc[m][n][c] = 0.f;

#pragma unroll 8
        for (int ks = 0; ks < 32; ks++) {
            uint32_t ko = (uint32_t)(ks * 32);
            uint32_t a0[4], a1[4], b0[4], b1[4];
            ldsm_x4(a0[0], a0[1], a0[2], a0[3], aAddr0 + ko);
            ldsm_x4(a1[0], a1[1], a1[2], a1[3], aAddr1 + ko);
            ldsm_x4(b0[0], b0[1], b0[2], b0[3], bAddr0 + ko);
            ldsm_x4(b1[0], b1[1], b1[2], b1[3], bAddr1 + ko);
            mma_tf32(acc[0][0], a0[0], a0[1], a0[2], a0[3], b0[0], b0[1]);
            mma_tf32(acc[0][1], a0[0], a0[1], a0[2], a0[3], b0[2], b0[3]);
            mma_tf32(acc[0][2], a0[0], a0[1], a0[2], a0[3], b1[0], b1[1]);
            mma_tf32(acc[0][3], a0[0], a0[1], a0[2], a0[3], b1[2], b1[3]);
            mma_tf32(acc[1][0], a1[0], a1[1], a1[2], a1[3], b0[0], b0[1]);
            mma_tf32(acc[1][1], a1[0], a1[1], a1[2], a1[3], b0[2], b0[3]);
            mma_tf32(acc[1][2], a1[0], a1[1], a1[2], a1[3], b1[0], b1[1]);
            mma_tf32(acc[1][3], a1[0], a1[1], a1[2], a1[3], b1[2], b1[3]);
        }

        // ---- epilogue: sum_j e1[i,j]*v1[j]*G[i,j] ----
#pragma unroll
        for (int mt = 0; mt < 2; mt++) {
            float p0 = 0.f, p1 = 0.f;
            int i0 = wi * 32 + mt * 16 + (lane >> 2);
#pragma unroll
            for (int nt = 0; nt < 4; nt++) {
                int j = wj * 32 + nt * 8 + (lane & 3) * 2;
                float vj0 = v1s[j], vj1 = v1s[j + 1];
                p0 += acc[mt][nt][0] * er[mt][nt][0] * vj0
                    + acc[mt][nt][1] * er[mt][nt][1] * vj1;
                p1 += acc[mt][nt][2] * er[mt][nt][2] * vj0
                    + acc[mt][nt][3] * er[mt][nt][3] * vj1;
            }
            p0 += __shfl_xor_sync(0xffffffffu, p0, 1);
            p0 += __shfl_xor_sync(0xffffffffu, p0, 2);
            p1 += __shfl_xor_sync(0xffffffffu, p1, 1);
            p1 += __shfl_xor_sync(0xffffffffu, p1, 2);
            if ((lane & 3) == 0) {
                red[i0 * 2 + wj] = p0;
                red[(i0 + 8) * 2 + wj] = p1;
            }
        }
        __syncthreads();
        if (t < 128) {
            float s = red[t * 2] + red[t * 2 + 1];
            int ig = ih * 128 + t;
            if (d < 64) g_numP[jh][((size_t)bh * NS + ig) * DH + d] = s;
            else        g_denP[jh][(size_t)bh * NS + ig] = s;
        }
        __syncthreads();
    }
}

// ---------------- normalize: combine 4 jh partials, o = num/den ----------------
__global__ void normalize_kernel() {
    int idx = blockIdx.x * 256 + threadIdx.x;   // 0..262143
    int dd = idx & 63;
    int i  = (idx >> 6) & 255;
    int bh = idx >> 14;
    int b = bh >> 3, h = bh & 7;
    float num = g_numP[0][idx] + g_numP[1][idx] + g_numP[2][idx] + g_numP[3][idx];
    float den = g_denP[0][bh * NS + i] + g_denP[1][bh * NS + i]
              + g_denP[2][bh * NS + i] + g_denP[3][bh * NS + i];
    g_o[(size_t)(b * 256 + i) * 512 + h * 64 + dd] = num / den;
}

extern "C" void kernel_launch(void* const* d_in, const int* in_sizes, int n_in,
                              void* d_out, int out_size) {
    const float* x     = (const float*)d_in[0];
    const float* w_qkv = (const float*)d_in[1];
    const float* w_out = (const float*)d_in[2];
    const float* qw    = (const float*)d_in[3];
    const float* k1w   = (const float*)d_in[4];
    const float* k2w   = (const float*)d_in[5];
    float* out = (float*)d_out;

    float *qkv_p = nullptr, *o_p = nullptr;
    cudaGetSymbolAddress((void**)&qkv_p, g_qkv);
    cudaGetSymbolAddress((void**)&o_p, g_o);

    cudaFuncSetAttribute(heavy_mma, cudaFuncAttributeMaxDynamicSharedMemorySize, SMEM_SZ);

    // 1) qkv = x @ w_qkv   [512,512]@[512,2560]
    sgemm128x64<<<dim3(40, 4), 256>>>(x, w_qkv, qkv_p, 512, 2560, 512);
    // 2) split + rmsnorm + pack
    pack_norm<<<4096, 64>>>(qw, k1w, k2w);
    // 3) e1/e2/e3
    sims_kernel<<<dim3(4, 2, 48), 256>>>();
    // 4) heavy factorized attention: 5 dgroups x (ih 2 x jh 4) x bh 16
    heavy_mma<<<dim3(5, 8, 16), 256, SMEM_SZ>>>();
    // 5) normalize (sum 4 jh partials)
    normalize_kernel<<<1024, 256>>>();
    // 6) out = o @ w_out   [512,512]@[512,512]
    sgemm128x64<<<dim3(8, 4), 256>>>(o_p, w_out, out, 512, 512, 512);
}

// round 11
// speedup vs baseline: 1.5138x; 1.5138x over previous
#include <cuda_runtime.h>
#include <cstdint>

#define BH 16
#define NS 256
#define DH 64
#define EPSF 1.1920929e-07f

// ---------------- scratch (device globals; no allocs) ----------------
__device__ __align__(16) float g_qkv[512 * 2560];
__device__ __align__(16) float g_qn [BH * NS * DH];
__device__ __align__(16) float g_k1 [BH * NS * DH];
__device__ __align__(16) float g_k2 [BH * NS * DH];
__device__ __align__(16) float g_v1t[BH * DH * NS];
__device__ __align__(16) float g_v2t[BH * DH * NS];
__device__ __align__(16) float g_e1 [BH * NS * NS];
__device__ __align__(16) float g_e2 [BH * NS * NS];
__device__ __align__(16) float g_e3 [BH * NS * NS];
__device__ __align__(16) float g_numP[4][BH * NS * DH];
__device__ __align__(16) float g_denP[4][BH * NS];
__device__ __align__(16) float g_o  [512 * 512];

__device__ __forceinline__ uint32_t cvt_tf32(float x) {
    uint32_t r; asm("cvt.rna.tf32.f32 %0, %1;" : "=r"(r) : "f"(x)); return r;
}
__device__ __forceinline__ uint32_t smem_u32(const void* p) {
    uint32_t a;
    asm("{ .reg .u64 t; cvta.to.shared.u64 t, %1; cvt.u32.u64 %0, t; }" : "=r"(a) : "l"(p));
    return a;
}
__device__ __forceinline__ void mma_tf32(float* c,
        uint32_t a0, uint32_t a1, uint32_t a2, uint32_t a3,
        uint32_t b0, uint32_t b1) {
    asm volatile("mma.sync.aligned.m16n8k8.row.col.f32.tf32.tf32.f32 "
        "{%0,%1,%2,%3}, {%4,%5,%6,%7}, {%8,%9}, {%0,%1,%2,%3};"
        : "+f"(c[0]), "+f"(c[1]), "+f"(c[2]), "+f"(c[3])
        : "r"(a0), "r"(a1), "r"(a2), "r"(a3), "r"(b0), "r"(b1));
}
__device__ __forceinline__ void ldsm_x4(uint32_t& r0, uint32_t& r1,
                                        uint32_t& r2, uint32_t& r3, uint32_t a) {
    asm volatile("ldmatrix.sync.aligned.m8n8.x4.shared.b16 {%0,%1,%2,%3}, [%4];"
                 : "=r"(r0), "=r"(r1), "=r"(r2), "=r"(r3) : "r"(a));
}

// ---------------- generic SGEMM: C[M,N] = A[M,K] @ B[K,N] ----------------
__global__ void sgemm128x64(const float* __restrict__ A, const float* __restrict__ B,
                            float* __restrict__ C, int M, int N, int K) {
    __shared__ float As[16][128];
    __shared__ float Bs[16][64];
    int t = threadIdx.x;
    int tx = t & 15, ty = t >> 4;
    int m0 = blockIdx.y * 128, n0 = blockIdx.x * 64;

    float acc[8][4];
#pragma unroll
    for (int i = 0; i < 8; i++)
#pragma unroll
        for (int j = 0; j < 4; j++) acc[i][j] = 0.f;

    for (int kt = 0; kt < K; kt += 16) {
#pragma unroll
        for (int q = 0; q < 2; q++) {
            int lin = t + q * 256;
            int m = lin & 127, kq = lin >> 7;
            float4 v = *(const float4*)&A[(size_t)(m0 + m) * K + kt + kq * 4];
            As[kq * 4 + 0][m] = v.x; As[kq * 4 + 1][m] = v.y;
            As[kq * 4 + 2][m] = v.z; As[kq * 4 + 3][m] = v.w;
        }
        {
            int kk = t >> 4, nq = t & 15;
            float4 v = *(const float4*)&B[(size_t)(kt + kk) * N + n0 + nq * 4];
            *(float4*)&Bs[kk][nq * 4] = v;
        }
        __syncthreads();
#pragma unroll
        for (int kk = 0; kk < 16; kk++) {
            float4 b = *(float4*)&Bs[kk][tx * 4];
            float a[8];
#pragma unroll
            for (int i = 0; i < 8; i++) a[i] = As[kk][ty * 8 + i];
#pragma unroll
            for (int i = 0; i < 8; i++) {
                acc[i][0] += a[i] * b.x; acc[i][1] += a[i] * b.y;
                acc[i][2] += a[i] * b.z; acc[i][3] += a[i] * b.w;
            }
        }
        __syncthreads();
    }
#pragma unroll
    for (int i = 0; i < 8; i++) {
        float4 v = make_float4(acc[i][0], acc[i][1], acc[i][2], acc[i][3]);
        *(float4*)&C[(size_t)(m0 + ty * 8 + i) * N + n0 + tx * 4] = v;
    }
}

// ---------------- split + rmsnorm + pack ----------------
__global__ void pack_norm(const float* __restrict__ qw,
                          const float* __restrict__ k1w,
                          const float* __restrict__ k2w) {
    int blk = blockIdx.x;
    int bh = blk >> 8, n = blk & 255;
    int b = bh >> 3, h = bh & 7;
    int dd = threadIdx.x;
    size_t base = (size_t)(b * 256 + n) * 2560 + h * 64 + dd;
    float q  = g_qkv[base];
    float k1 = g_qkv[base + 512];
    float k2 = g_qkv[base + 1024];
    float v1 = g_qkv[base + 1536];
    float v2 = g_qkv[base + 2048];

    __shared__ float sw[3][2];
    float sq = q * q, s1 = k1 * k1, s2 = k2 * k2;
#pragma unroll
    for (int o = 16; o; o >>= 1) {
        sq += __shfl_xor_sync(0xffffffffu, sq, o);
        s1 += __shfl_xor_sync(0xffffffffu, s1, o);
        s2 += __shfl_xor_sync(0xffffffffu, s2, o);
    }
    int w = dd >> 5;
    if ((dd & 31) == 0) { sw[0][w] = sq; sw[1][w] = s1; sw[2][w] = s2; }
    __syncthreads();
    float rq = rsqrtf((sw[0][0] + sw[0][1]) * (1.f / 64.f) + EPSF);
    float r1 = rsqrtf((sw[1][0] + sw[1][1]) * (1.f / 64.f) + EPSF);
    float r2 = rsqrtf((sw[2][0] + sw[2][1]) * (1.f / 64.f) + EPSF);

    int rb = bh * NS * DH + n * DH + dd;
    g_qn[rb] = q * rq * qw[dd] * 0.125f;
    g_k1[rb] = k1 * r1 * k1w[dd];
    g_k2[rb] = k2 * r2 * k2w[dd];
    g_v1t[bh * DH * NS + dd * NS + n] = v1;
    g_v2t[bh * DH * NS + dd * NS + n] = v2;
}

// ---------------- sims: e = exp(clip(scale * L @ R^T)) ----------------
__global__ void sims_kernel() {
    int z = blockIdx.z;
    int bh = z / 3, mat = z % 3;
    const float* L = ((mat == 2) ? g_k1 : g_qn) + bh * NS * DH;
    const float* R = ((mat == 0) ? g_k1 : g_k2) + bh * NS * DH;
    float* C = ((mat == 0) ? g_e1 : (mat == 1) ? g_e2 : g_e3) + (size_t)bh * NS * NS;
    float scale = (mat == 2) ? 0.125f : 1.f;

    __shared__ float As[16][128];
    __shared__ float Bs[16][64];
    int t = threadIdx.x, tx = t & 15, ty = t >> 4;
    int m0 = blockIdx.y * 128, n0 = blockIdx.x * 64;

    float acc[8][4];
#pragma unroll
    for (int i = 0; i < 8; i++)
#pragma unroll
        for (int j = 0; j < 4; j++) acc[i][j] = 0.f;

    for (int kt = 0; kt < 64; kt += 16) {
#pragma unroll
        for (int q = 0; q < 2; q++) {
            int lin = t + q * 256;
            int m = lin & 127, kq = lin >> 7;
            float4 v = *(const float4*)&L[(m0 + m) * 64 + kt + kq * 4];
            As[kq * 4 + 0][m] = v.x; As[kq * 4 + 1][m] = v.y;
            As[kq * 4 + 2][m] = v.z; As[kq * 4 + 3][m] = v.w;
        }
        {
            int n = t & 63, kq = t >> 6;
            float4 v = *(const float4*)&R[(n0 + n) * 64 + kt + kq * 4];
            Bs[kq * 4 + 0][n] = v.x; Bs[kq * 4 + 1][n] = v.y;
            Bs[kq * 4 + 2][n] = v.z; Bs[kq * 4 + 3][n] = v.w;
        }
        __syncthreads();
#pragma unroll
        for (int kk = 0; kk < 16; kk++) {
            float4 b = *(float4*)&Bs[kk][tx * 4];
            float a[8];
#pragma unroll
            for (int i = 0; i < 8; i++) a[i] = As[kk][ty * 8 + i];
#pragma unroll
            for (int i = 0; i < 8; i++) {
                acc[i][0] += a[i] * b.x; acc[i][1] += a[i] * b.y;
                acc[i][2] += a[i] * b.z; acc[i][3] += a[i] * b.w;
            }
        }
        __syncthreads();
    }
#pragma unroll
    for (int i = 0; i < 8; i++) {
        float4 v;
        v.x = __expf(fminf(40.f, fmaxf(-40.f, acc[i][0] * scale)));
        v.y = __expf(fminf(40.f, fmaxf(-40.f, acc[i][1] * scale)));
        v.z = __expf(fminf(40.f, fmaxf(-40.f, acc[i][2] * scale)));
        v.w = __expf(fminf(40.f, fmaxf(-40.f, acc[i][3] * scale)));
        *(float4*)&C[(size_t)(m0 + ty * 8 + i) * NS + n0 + tx * 4] = v;
    }
}

// ---------------- heavy: mma.sync tf32 + ldmatrix, all-SMEM-resident ----------------
// CTA (dg, ih, jh, bh): tile 64(i) x 64(j), 13 channels d. 512 threads,
// warp grid 4(i) x 4(j), warp tile 16x16 (2 MMA + 2 LDSM.x4 per k-step).
//   G[i,j] = sum_k (e2[i,k]*v2[k,d]) * e3[j,k]
//   partial[i] = sum_j e1[i,j]*v1[j,d]*G[i,j]   (e1 frags in regs, d-invariant)
// smem: A tf32 (64x260) + e3 tf32 (64x260) + e2 fp32 (64x260).
#define PCH 260
#define AS_OFF 0
#define E3_OFF 66560
#define E2_OFF 133120
#define V2_OFF 199680
#define V1_OFF 200704
#define RED_OFF 200960
#define SMEM_SZ 201984

__global__ void __launch_bounds__(512, 1) heavy_mma() {
    extern __shared__ __align__(16) char smem[];
    const uint32_t sb = smem_u32(smem);
    uint32_t* Asu = (uint32_t*)(smem + AS_OFF);
    uint32_t* E3u = (uint32_t*)(smem + E3_OFF);
    float*    E2f = (float*)(smem + E2_OFF);
    float*    v2s = (float*)(smem + V2_OFF);
    float*    v1s = (float*)(smem + V1_OFF);
    float*    red = (float*)(smem + RED_OFF);

    int t = threadIdx.x, lane = t & 31, wid = t >> 5;
    int wi = wid >> 2, wj = wid & 3;            // warp grid 4(i) x 4(j)
    int i0 = wi * 16, j0 = wj * 16;
    int dg = blockIdx.x;                        // 0..4, 13 channels each
    int ih = blockIdx.y >> 2, jh = blockIdx.y & 3;
    int bh = blockIdx.z;

    const float* e2p = g_e2 + (size_t)bh * 65536 + (size_t)(ih * 64) * 256;
    const float* e3p = g_e3 + (size_t)bh * 65536 + (size_t)(jh * 64) * 256;
    const float* e1p = g_e1 + (size_t)bh * 65536 + (size_t)(ih * 64) * 256 + jh * 64;

    // ---- CTA-start: e2 -> smem fp32, e3 -> smem tf32 ----
    for (int idx = t; idx < 4096; idx += 512) {     // 64 rows x 64 float4
        int r = idx >> 6, q = (idx & 63) << 2;
        float4 a = *(const float4*)&e2p[r * 256 + q];
        *(float4*)&E2f[r * PCH + q] = a;
        float4 b = *(const float4*)&e3p[r * 256 + q];
        uint4 u;
        u.x = cvt_tf32(b.x); u.y = cvt_tf32(b.y);
        u.z = cvt_tf32(b.z); u.w = cvt_tf32(b.w);
        *(uint4*)&E3u[r * PCH + q] = u;
    }

    // ---- e1 fragments in registers (d-independent, reused for 13 channels) ----
    float er[2][4];
    {
        int ir = i0 + (lane >> 2);
#pragma unroll
        for (int nt = 0; nt < 2; nt++) {
            int j = j0 + nt * 8 + (lane & 3) * 2;
            float2 w0 = *(const float2*)&e1p[(size_t)ir * 256 + j];
            float2 w1 = *(const float2*)&e1p[(size_t)(ir + 8) * 256 + j];
            er[nt][0] = w0.x; er[nt][1] = w0.y;
            er[nt][2] = w1.x; er[nt][3] = w1.y;
        }
    }

    // ---- ldmatrix lane addresses (validated mapping) ----
    int lr = lane & 7;
    uint32_t aRow = (uint32_t)(i0 + ((lane >> 3) & 1) * 8 + lr);
    uint32_t aK   = (uint32_t)((lane >> 4) * 4);
    uint32_t aAddr = sb + AS_OFF + (aRow * PCH + aK) * 4;
    uint32_t bRow = (uint32_t)(j0 + ((lane >> 4) & 1) * 8 + lr);
    uint32_t bK   = (uint32_t)(((lane >> 3) & 1) * 4);
    uint32_t bAddr = sb + E3_OFF + (bRow * PCH + bK) * 4;

    // A-build assignment: row = t&63, k-chunk = (t>>6)*32 (8 float4 each)
    int brow = t & 63, bkb = (t >> 6) << 5;
    const float* e2row = E2f + brow * PCH + bkb;
    uint32_t*    asrow = Asu + (uint32_t)(brow * PCH + bkb);

    for (int ci = 0; ci < 13; ci++) {
        int d = dg * 13 + ci;
        if (t < 64)  v1s[t] = (d < 64) ? g_v1t[((size_t)bh * DH + d) * NS + jh * 64 + t] : 1.f;
        else if (t >= 256 && t < 512 - 0 && (t - 256) < 256) {
            int k = t - 256;
            v2s[k] = (d < 64) ? g_v2t[((size_t)bh * DH + d) * NS + k] : 1.f;
        }
        __syncthreads();

        // build A = tf32(e2 * v2_d) from smem e2
#pragma unroll
        for (int q = 0; q < 8; q++) {
            float4 a = *(const float4*)(e2row + q * 4);
            float4 w = *(const float4*)&v2s[bkb + q * 4];
            uint4 u;
            u.x = cvt_tf32(a.x * w.x); u.y = cvt_tf32(a.y * w.y);
            u.z = cvt_tf32(a.z * w.z); u.w = cvt_tf32(a.w * w.w);
            *(uint4*)(asrow + q * 4) = u;
        }
        __syncthreads();

        // ---- MMA mainloop: 32 k-steps of 8, 2 LDSM.x4 + 2 MMA each ----
        float acc[2][4];
#pragma unroll
        for (int n = 0; n < 2; n++)
#pragma unroll
            for (int c = 0; c < 4; c++) acc[n][c] = 0.f;

#pragma unroll 8
        for (int ks = 0; ks < 32; ks++) {
            uint32_t ko = (uint32_t)(ks * 32);
            uint32_t a0, a1, a2, a3, b0, b1, b2, b3;
            ldsm_x4(a0, a1, a2, a3, aAddr + ko);
            ldsm_x4(b0, b1, b2, b3, bAddr + ko);
            mma_tf32(acc[0], a0, a1, a2, a3, b0, b1);
            mma_tf32(acc[1], a0, a1, a2, a3, b2, b3);
        }

        // ---- epilogue: sum_j e1[i,j]*v1[j]*G[i,j] ----
        float p0 = 0.f, p1 = 0.f;
#pragma unroll
        for (int nt = 0; nt < 2; nt++) {
            int j = j0 + nt * 8 + (lane & 3) * 2;
            float vj0 = v1s[j], vj1 = v1s[j + 1];
            p0 += acc[nt][0] * er[nt][0] * vj0 + acc[nt][1] * er[nt][1] * vj1;
            p1 += acc[nt][2] * er[nt][2] * vj0 + acc[nt][3] * er[nt][3] * vj1;
        }
        p0 += __shfl_xor_sync(0xffffffffu, p0, 1);
        p0 += __shfl_xor_sync(0xffffffffu, p0, 2);
        p1 += __shfl_xor_sync(0xffffffffu, p1, 1);
        p1 += __shfl_xor_sync(0xffffffffu, p1, 2);
        if ((lane & 3) == 0) {
            int il = i0 + (lane >> 2);
            red[il * 4 + wj] = p0;
            red[(il + 8) * 4 + wj] = p1;
        }
        __syncthreads();
        if (t < 64) {
            float s = red[t * 4] + red[t * 4 + 1] + red[t * 4 + 2] + red[t * 4 + 3];
            int ig = ih * 64 + t;
            if (d < 64) g_numP[jh][((size_t)bh * NS + ig) * DH + d] = s;
            else        g_denP[jh][(size_t)bh * NS + ig] = s;
        }
        __syncthreads();
    }
}

// ---------------- normalize: combine 4 jh partials, o = num/den ----------------
__global__ void normalize_kernel() {
    int idx = blockIdx.x * 256 + threadIdx.x;   // 0..262143
    int dd = idx & 63;
    int i  = (idx >> 6) & 255;
    int bh = idx >> 14;
    int b = bh >> 3, h = bh & 7;
    float num = g_numP[0][idx] + g_numP[1][idx] + g_numP[2][idx] + g_numP[3][idx];
    float den = g_denP[0][bh * NS + i] + g_denP[1][bh * NS + i]
              + g_denP[2][bh * NS + i] + g_denP[3][bh * NS + i];
    g_o[(size_t)(b * 256 + i) * 512 + h * 64 + dd] = num / den;
}

extern "C" void kernel_launch(void* const* d_in, const int* in_sizes, int n_in,
                              void* d_out, int out_size) {
    const float* x     = (const float*)d_in[0];
    const float* w_qkv = (const float*)d_in[1];
    const float* w_out = (const float*)d_in[2];
    const float* qw    = (const float*)d_in[3];
    const float* k1w   = (const float*)d_in[4];
    const float* k2w   = (const float*)d_in[5];
    float* out = (float*)d_out;

    float *qkv_p = nullptr, *o_p = nullptr;
    cudaGetSymbolAddress((void**)&qkv_p, g_qkv);
    cudaGetSymbolAddress((void**)&o_p, g_o);

    cudaFuncSetAttribute(heavy_mma, cudaFuncAttributeMaxDynamicSharedMemorySize, SMEM_SZ);

    // 1) qkv = x @ w_qkv   [512,512]@[512,2560]
    sgemm128x64<<<dim3(40, 4), 256>>>(x, w_qkv, qkv_p, 512, 2560, 512);
    // 2) split + rmsnorm + pack
    pack_norm<<<4096, 64>>>(qw, k1w, k2w);
    // 3) e1/e2/e3
    sims_kernel<<<dim3(4, 2, 48), 256>>>();
    // 4) heavy factorized attention: 5 dgroups x (ih 4 x jh 4) x bh 16
    heavy_mma<<<dim3(5, 16, 16), 512, SMEM_SZ>>>();
    // 5) normalize (sum 4 jh partials)
    normalize_kernel<<<1024, 256>>>();
    // 6) out = o @ w_out   [512,512]@[512,512]
    sgemm128x64<<<dim3(8, 4), 256>>>(o_p, w_out, out, 512, 512, 512);
}

// round 12
// speedup vs baseline: 2.1642x; 1.4297x over previous
#include <cuda_runtime.h>
#include <cstdint>

#define BH 16
#define NS 256
#define DH 64
#define EPSF 1.1920929e-07f

// ---------------- scratch (device globals; no allocs) ----------------
__device__ __align__(16) float g_qkv[512 * 2560];
__device__ __align__(16) float g_qn [BH * NS * DH];
__device__ __align__(16) float g_k1 [BH * NS * DH];
__device__ __align__(16) float g_k2 [BH * NS * DH];
__device__ __align__(16) float g_v1t[BH * DH * NS];
__device__ __align__(16) float g_v2t[BH * DH * NS];
__device__ __align__(16) float g_e1 [BH * NS * NS];
__device__ __align__(16) float g_e2 [BH * NS * NS];
__device__ __align__(16) float g_e3 [BH * NS * NS];
__device__ __align__(16) float g_numP[2][BH * NS * DH];
__device__ __align__(16) float g_denP[2][BH * NS];
__device__ __align__(16) float g_o  [512 * 512];

__device__ __forceinline__ uint32_t cvt_tf32(float x) {
    uint32_t r; asm("cvt.rna.tf32.f32 %0, %1;" : "=r"(r) : "f"(x)); return r;
}
__device__ __forceinline__ uint32_t smem_u32(const void* p) {
    uint32_t a;
    asm("{ .reg .u64 t; cvta.to.shared.u64 t, %1; cvt.u32.u64 %0, t; }" : "=r"(a) : "l"(p));
    return a;
}
__device__ __forceinline__ void mma_tf32(float* c,
        uint32_t a0, uint32_t a1, uint32_t a2, uint32_t a3,
        uint32_t b0, uint32_t b1) {
    asm volatile("mma.sync.aligned.m16n8k8.row.col.f32.tf32.tf32.f32 "
        "{%0,%1,%2,%3}, {%4,%5,%6,%7}, {%8,%9}, {%0,%1,%2,%3};"
        : "+f"(c[0]), "+f"(c[1]), "+f"(c[2]), "+f"(c[3])
        : "r"(a0), "r"(a1), "r"(a2), "r"(a3), "r"(b0), "r"(b1));
}
__device__ __forceinline__ void ldsm_x4(uint32_t& r0, uint32_t& r1,
                                        uint32_t& r2, uint32_t& r3, uint32_t a) {
    asm volatile("ldmatrix.sync.aligned.m8n8.x4.shared.b16 {%0,%1,%2,%3}, [%4];"
                 : "=r"(r0), "=r"(r1), "=r"(r2), "=r"(r3) : "r"(a));
}

// ---------------- generic SGEMM: C[M,N] = A[M,K] @ B[K,N] ----------------
__global__ void sgemm128x64(const float* __restrict__ A, const float* __restrict__ B,
                            float* __restrict__ C, int M, int N, int K) {
    __shared__ float As[16][128];
    __shared__ float Bs[16][64];
    int t = threadIdx.x;
    int tx = t & 15, ty = t >> 4;
    int m0 = blockIdx.y * 128, n0 = blockIdx.x * 64;

    float acc[8][4];
#pragma unroll
    for (int i = 0; i < 8; i++)
#pragma unroll
        for (int j = 0; j < 4; j++) acc[i][j] = 0.f;

    for (int kt = 0; kt < K; kt += 16) {
#pragma unroll
        for (int q = 0; q < 2; q++) {
            int lin = t + q * 256;
            int m = lin & 127, kq = lin >> 7;
            float4 v = *(const float4*)&A[(size_t)(m0 + m) * K + kt + kq * 4];
            As[kq * 4 + 0][m] = v.x; As[kq * 4 + 1][m] = v.y;
            As[kq * 4 + 2][m] = v.z; As[kq * 4 + 3][m] = v.w;
        }
        {
            int kk = t >> 4, nq = t & 15;
            float4 v = *(const float4*)&B[(size_t)(kt + kk) * N + n0 + nq * 4];
            *(float4*)&Bs[kk][nq * 4] = v;
        }
        __syncthreads();
#pragma unroll
        for (int kk = 0; kk < 16; kk++) {
            float4 b = *(float4*)&Bs[kk][tx * 4];
            float a[8];
#pragma unroll
            for (int i = 0; i < 8; i++) a[i] = As[kk][ty * 8 + i];
#pragma unroll
            for (int i = 0; i < 8; i++) {
                acc[i][0] += a[i] * b.x; acc[i][1] += a[i] * b.y;
                acc[i][2] += a[i] * b.z; acc[i][3] += a[i] * b.w;
            }
        }
        __syncthreads();
    }
#pragma unroll
    for (int i = 0; i < 8; i++) {
        float4 v = make_float4(acc[i][0], acc[i][1], acc[i][2], acc[i][3]);
        *(float4*)&C[(size_t)(m0 + ty * 8 + i) * N + n0 + tx * 4] = v;
    }
}

// ---------------- split + rmsnorm + pack ----------------
__global__ void pack_norm(const float* __restrict__ qw,
                          const float* __restrict__ k1w,
                          const float* __restrict__ k2w) {
    int blk = blockIdx.x;
    int bh = blk >> 8, n = blk & 255;
    int b = bh >> 3, h = bh & 7;
    int dd = threadIdx.x;
    size_t base = (size_t)(b * 256 + n) * 2560 + h * 64 + dd;
    float q  = g_qkv[base];
    float k1 = g_qkv[base + 512];
    float k2 = g_qkv[base + 1024];
    float v1 = g_qkv[base + 1536];
    float v2 = g_qkv[base + 2048];

    __shared__ float sw[3][2];
    float sq = q * q, s1 = k1 * k1, s2 = k2 * k2;
#pragma unroll
    for (int o = 16; o; o >>= 1) {
        sq += __shfl_xor_sync(0xffffffffu, sq, o);
        s1 += __shfl_xor_sync(0xffffffffu, s1, o);
        s2 += __shfl_xor_sync(0xffffffffu, s2, o);
    }
    int w = dd >> 5;
    if ((dd & 31) == 0) { sw[0][w] = sq; sw[1][w] = s1; sw[2][w] = s2; }
    __syncthreads();
    float rq = rsqrtf((sw[0][0] + sw[0][1]) * (1.f / 64.f) + EPSF);
    float r1 = rsqrtf((sw[1][0] + sw[1][1]) * (1.f / 64.f) + EPSF);
    float r2 = rsqrtf((sw[2][0] + sw[2][1]) * (1.f / 64.f) + EPSF);

    int rb = bh * NS * DH + n * DH + dd;
    g_qn[rb] = q * rq * qw[dd] * 0.125f;
    g_k1[rb] = k1 * r1 * k1w[dd];
    g_k2[rb] = k2 * r2 * k2w[dd];
    g_v1t[bh * DH * NS + dd * NS + n] = v1;
    g_v2t[bh * DH * NS + dd * NS + n] = v2;
}

// ---------------- sims: e = exp(clip(scale * L @ R^T)) ----------------
__global__ void sims_kernel() {
    int z = blockIdx.z;
    int bh = z / 3, mat = z % 3;
    const float* L = ((mat == 2) ? g_k1 : g_qn) + bh * NS * DH;
    const float* R = ((mat == 0) ? g_k1 : g_k2) + bh * NS * DH;
    float* C = ((mat == 0) ? g_e1 : (mat == 1) ? g_e2 : g_e3) + (size_t)bh * NS * NS;
    float scale = (mat == 2) ? 0.125f : 1.f;

    __shared__ float As[16][128];
    __shared__ float Bs[16][64];
    int t = threadIdx.x, tx = t & 15, ty = t >> 4;
    int m0 = blockIdx.y * 128, n0 = blockIdx.x * 64;

    float acc[8][4];
#pragma unroll
    for (int i = 0; i < 8; i++)
#pragma unroll
        for (int j = 0; j < 4; j++) acc[i][j] = 0.f;

    for (int kt = 0; kt < 64; kt += 16) {
#pragma unroll
        for (int q = 0; q < 2; q++) {
            int lin = t + q * 256;
            int m = lin & 127, kq = lin >> 7;
            float4 v = *(const float4*)&L[(m0 + m) * 64 + kt + kq * 4];
            As[kq * 4 + 0][m] = v.x; As[kq * 4 + 1][m] = v.y;
            As[kq * 4 + 2][m] = v.z; As[kq * 4 + 3][m] = v.w;
        }
        {
            int n = t & 63, kq = t >> 6;
            float4 v = *(const float4*)&R[(n0 + n) * 64 + kt + kq * 4];
            Bs[kq * 4 + 0][n] = v.x; Bs[kq * 4 + 1][n] = v.y;
            Bs[kq * 4 + 2][n] = v.z; Bs[kq * 4 + 3][n] = v.w;
        }
        __syncthreads();
#pragma unroll
        for (int kk = 0; kk < 16; kk++) {
            float4 b = *(float4*)&Bs[kk][tx * 4];
            float a[8];
#pragma unroll
            for (int i = 0; i < 8; i++) a[i] = As[kk][ty * 8 + i];
#pragma unroll
            for (int i = 0; i < 8; i++) {
                acc[i][0] += a[i] * b.x; acc[i][1] += a[i] * b.y;
                acc[i][2] += a[i] * b.z; acc[i][3] += a[i] * b.w;
            }
        }
        __syncthreads();
    }
#pragma unroll
    for (int i = 0; i < 8; i++) {
        float4 v;
        v.x = __expf(fminf(40.f, fmaxf(-40.f, acc[i][0] * scale)));
        v.y = __expf(fminf(40.f, fmaxf(-40.f, acc[i][1] * scale)));
        v.z = __expf(fminf(40.f, fmaxf(-40.f, acc[i][2] * scale)));
        v.w = __expf(fminf(40.f, fmaxf(-40.f, acc[i][3] * scale)));
        *(float4*)&C[(size_t)(m0 + ty * 8 + i) * NS + n0 + tx * 4] = v;
    }
}

// ---------------- heavy: mma.sync tf32 + ldmatrix, low-traffic ----------------
// CTA (dg, ib, jb, bh): tile 64(i) x 128(j), 256 threads, 8 warps,
// warp grid 2(i) x 4(j), warp tile 32x32 (4 LDSM.x4 + 8 MMA per k-step).
//   G[i,j] = sum_k (e2[i,k]*v2[k,d]) * e3[j,k]
// B = tf32(e3) [128x256] built ONCE (static across 13 channels).
// A = tf32(e2*v2_d) rebuilt per channel per k-half from REGISTER-resident raw e2.
#define BPCH 260
#define APCH 132
#define B_OFF 0
#define A_OFF 133120
#define RED_OFF 200704
#define V2_OFF 201728
#define SMEM_SZ 202752

__global__ void __launch_bounds__(256, 1) heavy_mma() {
    extern __shared__ __align__(16) char smem[];
    const uint32_t sb = smem_u32(smem);
    uint32_t* Bu  = (uint32_t*)(smem + B_OFF);
    uint32_t* Au  = (uint32_t*)(smem + A_OFF);
    float*    red = (float*)(smem + RED_OFF);
    float*    v2s = (float*)(smem + V2_OFF);

    int t = threadIdx.x, lane = t & 31, wid = t >> 5;
    int wi = wid >> 2, wj = wid & 3;            // 2(i) x 4(j)
    int i0 = wi * 32, j0 = wj * 32;
    int dg = blockIdx.x;                        // 0..4, 13 channels each
    int ib = blockIdx.y >> 1, jb = blockIdx.y & 1;
    int bh = blockIdx.z;

    const float* e2p = g_e2 + (size_t)bh * 65536 + (size_t)(ib * 64) * 256;
    const float* e3p = g_e3 + (size_t)bh * 65536 + (size_t)(jb * 128) * 256;
    const float* e1p = g_e1 + (size_t)bh * 65536 + (size_t)(ib * 64) * 256 + jb * 128;
    const float* v1b = g_v1t + (size_t)bh * DH * NS;
    const float* v2b = g_v2t + (size_t)bh * DH * NS;

    // ---- B static: tf32(e3) [128 x 256] pitch 260, built once ----
    for (int idx = t; idx < 8192; idx += 256) {   // 128 rows x 64 float4
        int r = idx >> 6, q = (idx & 63) << 2;
        float4 b = *(const float4*)&e3p[r * 256 + q];
        uint4 u;
        u.x = cvt_tf32(b.x); u.y = cvt_tf32(b.y);
        u.z = cvt_tf32(b.z); u.w = cvt_tf32(b.w);
        *(uint4*)&Bu[r * BPCH + q] = u;
    }

    // ---- raw e2 tile -> registers (once): thread owns row=wid+8q, cols lane*4.. ----
    float4 st0[8], st1[8];
#pragma unroll
    for (int q = 0; q < 8; q++) {
        int row = wid + 8 * q;
        st0[q] = *(const float4*)&e2p[row * 256 + lane * 4];
        st1[q] = *(const float4*)&e2p[row * 256 + 128 + lane * 4];
    }

    // ---- e1 fragments in registers (d-independent) ----
    float er[2][4][4];
#pragma unroll
    for (int mt = 0; mt < 2; mt++) {
        int ir = i0 + mt * 16 + (lane >> 2);
#pragma unroll
        for (int nt = 0; nt < 4; nt++) {
            int j = j0 + nt * 8 + (lane & 3) * 2;
            float2 w0 = *(const float2*)&e1p[(size_t)ir * 256 + j];
            float2 w1 = *(const float2*)&e1p[(size_t)(ir + 8) * 256 + j];
            er[mt][nt][0] = w0.x; er[mt][nt][1] = w0.y;
            er[mt][nt][2] = w1.x; er[mt][nt][3] = w1.y;
        }
    }

    // ---- v2 smem + v1 regs for channel 0 ----
    int d0 = dg * 13;
    v2s[t] = v2b[(size_t)d0 * NS + t];          // d0 <= 52 < 64 always
    float vr0[4], vr1[4];
#pragma unroll
    for (int nt = 0; nt < 4; nt++) {
        int jg = jb * 128 + j0 + nt * 8 + (lane & 3) * 2;
        vr0[nt] = v1b[(size_t)d0 * NS + jg];
        vr1[nt] = v1b[(size_t)d0 * NS + jg + 1];
    }

    // ---- ldmatrix lane addresses (R11-validated mapping) ----
    int lr = lane & 7;
    uint32_t aRow = (uint32_t)(i0 + ((lane >> 3) & 1) * 8 + lr);
    uint32_t aK   = (uint32_t)((lane >> 4) * 4);
    uint32_t aBase = sb + A_OFF + (aRow * APCH + aK) * 4;  // +half*33792 +mt*8448 +ks*32
    uint32_t bRow = (uint32_t)(j0 + ((lane >> 4) & 1) * 8 + lr);
    uint32_t bK   = (uint32_t)(((lane >> 3) & 1) * 4);
    uint32_t bBase = sb + B_OFF + (bRow * BPCH + bK) * 4;  // +ntp*16640 +half*512 +ks*32

    __syncthreads();   // B + v2s ready

    float acc[2][4][4];

#pragma unroll 1
    for (int ch = 0; ch < 13; ch++) {
        int d = dg * 13 + ch;

        // ===== half 0: build A = tf32(e2*v2) into buf0, then MMA =====
#pragma unroll
        for (int q = 0; q < 8; q++) {
            int row = wid + 8 * q;
            float4 a = st0[q];
            float4 w = *(const float4*)&v2s[lane * 4];
            uint4 u;
            u.x = cvt_tf32(a.x * w.x); u.y = cvt_tf32(a.y * w.y);
            u.z = cvt_tf32(a.z * w.z); u.w = cvt_tf32(a.w * w.w);
            *(uint4*)&Au[row * APCH + lane * 4] = u;
        }
        __syncthreads();

#pragma unroll
        for (int m = 0; m < 2; m++)
#pragma unroll
            for (int n = 0; n < 4; n++)
#pragma unroll
                for (int c = 0; c < 4; c++) acc[m][n][c] = 0.f;

#pragma unroll
        for (int ks = 0; ks < 16; ks++) {
            uint32_t ko = (uint32_t)(ks * 32);
            uint32_t a0,a1,a2,a3, a4,a5,a6,a7, b0,b1,b2,b3, b4,b5,b6,b7;
            ldsm_x4(a0,a1,a2,a3, aBase + ko);
            ldsm_x4(a4,a5,a6,a7, aBase + 8448 + ko);
            ldsm_x4(b0,b1,b2,b3, bBase + ko);
            ldsm_x4(b4,b5,b6,b7, bBase + 16640 + ko);
            mma_tf32(acc[0][0], a0,a1,a2,a3, b0,b1);
            mma_tf32(acc[0][1], a0,a1,a2,a3, b2,b3);
            mma_tf32(acc[0][2], a0,a1,a2,a3, b4,b5);
            mma_tf32(acc[0][3], a0,a1,a2,a3, b6,b7);
            mma_tf32(acc[1][0], a4,a5,a6,a7, b0,b1);
            mma_tf32(acc[1][1], a4,a5,a6,a7, b2,b3);
            mma_tf32(acc[1][2], a4,a5,a6,a7, b4,b5);
            mma_tf32(acc[1][3], a4,a5,a6,a7, b6,b7);
        }

        // ===== half 1: build A into buf1 (other warps may still read buf0) =====
#pragma unroll
        for (int q = 0; q < 8; q++) {
            int row = wid + 8 * q;
            float4 a = st1[q];
            float4 w = *(const float4*)&v2s[128 + lane * 4];
            uint4 u;
            u.x = cvt_tf32(a.x * w.x); u.y = cvt_tf32(a.y * w.y);
            u.z = cvt_tf32(a.z * w.z); u.w = cvt_tf32(a.w * w.w);
            *(uint4*)&Au[(64 + row) * APCH + lane * 4] = u;
        }
        __syncthreads();

#pragma unroll
        for (int ks = 0; ks < 16; ks++) {
            uint32_t ko = (uint32_t)(ks * 32);
            uint32_t a0,a1,a2,a3, a4,a5,a6,a7, b0,b1,b2,b3, b4,b5,b6,b7;
            ldsm_x4(a0,a1,a2,a3, aBase + 33792 + ko);
            ldsm_x4(a4,a5,a6,a7, aBase + 33792 + 8448 + ko);
            ldsm_x4(b0,b1,b2,b3, bBase + 512 + ko);
            ldsm_x4(b4,b5,b6,b7, bBase + 512 + 16640 + ko);
            mma_tf32(acc[0][0], a0,a1,a2,a3, b0,b1);
            mma_tf32(acc[0][1], a0,a1,a2,a3, b2,b3);
            mma_tf32(acc[0][2], a0,a1,a2,a3, b4,b5);
            mma_tf32(acc[0][3], a0,a1,a2,a3, b6,b7);
            mma_tf32(acc[1][0], a4,a5,a6,a7, b0,b1);
            mma_tf32(acc[1][1], a4,a5,a6,a7, b2,b3);
            mma_tf32(acc[1][2], a4,a5,a6,a7, b4,b5);
            mma_tf32(acc[1][3], a4,a5,a6,a7, b6,b7);
        }

        // ===== epilogue: partial[i] = sum_j e1*v1*G =====
#pragma unroll
        for (int mt = 0; mt < 2; mt++) {
            float p0 = 0.f, p1 = 0.f;
#pragma unroll
            for (int nt = 0; nt < 4; nt++) {
                p0 += acc[mt][nt][0] * er[mt][nt][0] * vr0[nt]
                    + acc[mt][nt][1] * er[mt][nt][1] * vr1[nt];
                p1 += acc[mt][nt][2] * er[mt][nt][2] * vr0[nt]
                    + acc[mt][nt][3] * er[mt][nt][3] * vr1[nt];
            }
            p0 += __shfl_xor_sync(0xffffffffu, p0, 1);
            p0 += __shfl_xor_sync(0xffffffffu, p0, 2);
            p1 += __shfl_xor_sync(0xffffffffu, p1, 1);
            p1 += __shfl_xor_sync(0xffffffffu, p1, 2);
            if ((lane & 3) == 0) {
                int il = i0 + mt * 16 + (lane >> 2);
                red[il * 4 + wj] = p0;
                red[(il + 8) * 4 + wj] = p1;
            }
        }
        __syncthreads();

        // final store + stage next channel's v1/v2
        if (t < 64) {
            float s = red[t * 4] + red[t * 4 + 1] + red[t * 4 + 2] + red[t * 4 + 3];
            int ig = ib * 64 + t;
            if (d < 64) g_numP[jb][((size_t)bh * NS + ig) * DH + d] = s;
            else        g_denP[jb][(size_t)bh * NS + ig] = s;
        }
        int d2 = d + 1;
        v2s[t] = (d2 < 64) ? v2b[(size_t)d2 * NS + t] : 1.f;
#pragma unroll
        for (int nt = 0; nt < 4; nt++) {
            int jg = jb * 128 + j0 + nt * 8 + (lane & 3) * 2;
            vr0[nt] = (d2 < 64) ? v1b[(size_t)d2 * NS + jg] : 1.f;
            vr1[nt] = (d2 < 64) ? v1b[(size_t)d2 * NS + jg + 1] : 1.f;
        }
        __syncthreads();
    }
}

// ---------------- normalize: combine 2 jb partials, o = num/den ----------------
__global__ void normalize_kernel() {
    int idx = blockIdx.x * 256 + threadIdx.x;   // 0..262143
    int dd = idx & 63;
    int i  = (idx >> 6) & 255;
    int bh = idx >> 14;
    int b = bh >> 3, h = bh & 7;
    float num = g_numP[0][idx] + g_numP[1][idx];
    float den = g_denP[0][bh * NS + i] + g_denP[1][bh * NS + i];
    g_o[(size_t)(b * 256 + i) * 512 + h * 64 + dd] = num / den;
}

extern "C" void kernel_launch(void* const* d_in, const int* in_sizes, int n_in,
                              void* d_out, int out_size) {
    const float* x     = (const float*)d_in[0];
    const float* w_qkv = (const float*)d_in[1];
    const float* w_out = (const float*)d_in[2];
    const float* qw    = (const float*)d_in[3];
    const float* k1w   = (const float*)d_in[4];
    const float* k2w   = (const float*)d_in[5];
    float* out = (float*)d_out;

    float *qkv_p = nullptr, *o_p = nullptr;
    cudaGetSymbolAddress((void**)&qkv_p, g_qkv);
    cudaGetSymbolAddress((void**)&o_p, g_o);

    cudaFuncSetAttribute(heavy_mma, cudaFuncAttributeMaxDynamicSharedMemorySize, SMEM_SZ);

    // 1) qkv = x @ w_qkv   [512,512]@[512,2560]
    sgemm128x64<<<dim3(40, 4), 256>>>(x, w_qkv, qkv_p, 512, 2560, 512);
    // 2) split + rmsnorm + pack
    pack_norm<<<4096, 64>>>(qw, k1w, k2w);
    // 3) e1/e2/e3
    sims_kernel<<<dim3(4, 2, 48), 256>>>();
    // 4) heavy: 5 dgroups x (ib 4 x jb 2) x bh 16 = 640 CTAs
    heavy_mma<<<dim3(5, 8, 16), 256, SMEM_SZ>>>();
    // 5) normalize (sum 2 jb partials)
    normalize_kernel<<<1024, 256>>>();
    // 6) out = o @ w_out   [512,512]@[512,512]
    sgemm128x64<<<dim3(8, 4), 256>>>(o_p, w_out, out, 512, 512, 512);
}

// round 13
// speedup vs baseline: 2.1659x; 1.0008x over previous
#include <cuda_runtime.h>
#include <cstdint>

#define BH 16
#define NS 256
#define DH 64
#define EPSF 1.1920929e-07f

// ---------------- scratch (device globals; no allocs) ----------------
__device__ __align__(16) float g_qkv[512 * 2560];
__device__ __align__(16) float g_qn [BH * NS * DH];
__device__ __align__(16) float g_k1 [BH * NS * DH];
__device__ __align__(16) float g_k2 [BH * NS * DH];
__device__ __align__(16) float g_v1t[BH * DH * NS];
__device__ __align__(16) float g_v2t[BH * DH * NS];
__device__ __align__(16) float g_e1 [BH * NS * NS];
__device__ __align__(16) float g_e2 [BH * NS * NS];
__device__ __align__(16) float g_e3 [BH * NS * NS];
__device__ __align__(16) float g_numP[2][BH * NS * DH];
__device__ __align__(16) float g_denP[2][BH * NS];
__device__ __align__(16) float g_o  [512 * 512];

__device__ __forceinline__ uint32_t cvt_tf32(float x) {
    uint32_t r; asm("cvt.rna.tf32.f32 %0, %1;" : "=r"(r) : "f"(x)); return r;
}
__device__ __forceinline__ uint32_t smem_u32(const void* p) {
    uint32_t a;
    asm("{ .reg .u64 t; cvta.to.shared.u64 t, %1; cvt.u32.u64 %0, t; }" : "=r"(a) : "l"(p));
    return a;
}
__device__ __forceinline__ void mma_tf32(float* c,
        uint32_t a0, uint32_t a1, uint32_t a2, uint32_t a3,
        uint32_t b0, uint32_t b1) {
    asm volatile("mma.sync.aligned.m16n8k8.row.col.f32.tf32.tf32.f32 "
        "{%0,%1,%2,%3}, {%4,%5,%6,%7}, {%8,%9}, {%0,%1,%2,%3};"
        : "+f"(c[0]), "+f"(c[1]), "+f"(c[2]), "+f"(c[3])
        : "r"(a0), "r"(a1), "r"(a2), "r"(a3), "r"(b0), "r"(b1));
}
__device__ __forceinline__ void ldsm_x4(uint32_t& r0, uint32_t& r1,
                                        uint32_t& r2, uint32_t& r3, uint32_t a) {
    asm volatile("ldmatrix.sync.aligned.m8n8.x4.shared.b16 {%0,%1,%2,%3}, [%4];"
                 : "=r"(r0), "=r"(r1), "=r"(r2), "=r"(r3) : "r"(a));
}

// ---------------- generic SGEMM: C[M,N] = A[M,K] @ B[K,N] ----------------
__global__ void sgemm128x64(const float* __restrict__ A, const float* __restrict__ B,
                            float* __restrict__ C, int M, int N, int K) {
    __shared__ float As[16][128];
    __shared__ float Bs[16][64];
    int t = threadIdx.x;
    int tx = t & 15, ty = t >> 4;
    int m0 = blockIdx.y * 128, n0 = blockIdx.x * 64;

    float acc[8][4];
#pragma unroll
    for (int i = 0; i < 8; i++)
#pragma unroll
        for (int j = 0; j < 4; j++) acc[i][j] = 0.f;

    for (int kt = 0; kt < K; kt += 16) {
#pragma unroll
        for (int q = 0; q < 2; q++) {
            int lin = t + q * 256;
            int m = lin & 127, kq = lin >> 7;
            float4 v = *(const float4*)&A[(size_t)(m0 + m) * K + kt + kq * 4];
            As[kq * 4 + 0][m] = v.x; As[kq * 4 + 1][m] = v.y;
            As[kq * 4 + 2][m] = v.z; As[kq * 4 + 3][m] = v.w;
        }
        {
            int kk = t >> 4, nq = t & 15;
            float4 v = *(const float4*)&B[(size_t)(kt + kk) * N + n0 + nq * 4];
            *(float4*)&Bs[kk][nq * 4] = v;
        }
        __syncthreads();
#pragma unroll
        for (int kk = 0; kk < 16; kk++) {
            float4 b = *(float4*)&Bs[kk][tx * 4];
            float a[8];
#pragma unroll
            for (int i = 0; i < 8; i++) a[i] = As[kk][ty * 8 + i];
#pragma unroll
            for (int i = 0; i < 8; i++) {
                acc[i][0] += a[i] * b.x; acc[i][1] += a[i] * b.y;
                acc[i][2] += a[i] * b.z; acc[i][3] += a[i] * b.w;
            }
        }
        __syncthreads();
    }
#pragma unroll
    for (int i = 0; i < 8; i++) {
        float4 v = make_float4(acc[i][0], acc[i][1], acc[i][2], acc[i][3]);
        *(float4*)&C[(size_t)(m0 + ty * 8 + i) * N + n0 + tx * 4] = v;
    }
}

// ---------------- split + rmsnorm + pack ----------------
__global__ void pack_norm(const float* __restrict__ qw,
                          const float* __restrict__ k1w,
                          const float* __restrict__ k2w) {
    int blk = blockIdx.x;
    int bh = blk >> 8, n = blk & 255;
    int b = bh >> 3, h = bh & 7;
    int dd = threadIdx.x;
    size_t base = (size_t)(b * 256 + n) * 2560 + h * 64 + dd;
    float q  = g_qkv[base];
    float k1 = g_qkv[base + 512];
    float k2 = g_qkv[base + 1024];
    float v1 = g_qkv[base + 1536];
    float v2 = g_qkv[base + 2048];

    __shared__ float sw[3][2];
    float sq = q * q, s1 = k1 * k1, s2 = k2 * k2;
#pragma unroll
    for (int o = 16; o; o >>= 1) {
        sq += __shfl_xor_sync(0xffffffffu, sq, o);
        s1 += __shfl_xor_sync(0xffffffffu, s1, o);
        s2 += __shfl_xor_sync(0xffffffffu, s2, o);
    }
    int w = dd >> 5;
    if ((dd & 31) == 0) { sw[0][w] = sq; sw[1][w] = s1; sw[2][w] = s2; }
    __syncthreads();
    float rq = rsqrtf((sw[0][0] + sw[0][1]) * (1.f / 64.f) + EPSF);
    float r1 = rsqrtf((sw[1][0] + sw[1][1]) * (1.f / 64.f) + EPSF);
    float r2 = rsqrtf((sw[2][0] + sw[2][1]) * (1.f / 64.f) + EPSF);

    int rb = bh * NS * DH + n * DH + dd;
    g_qn[rb] = q * rq * qw[dd] * 0.125f;
    g_k1[rb] = k1 * r1 * k1w[dd];
    g_k2[rb] = k2 * r2 * k2w[dd];
    g_v1t[bh * DH * NS + dd * NS + n] = v1;
    g_v2t[bh * DH * NS + dd * NS + n] = v2;
}

// ---------------- sims: e = exp(clip(scale * L @ R^T)) ----------------
__global__ void sims_kernel() {
    int z = blockIdx.z;
    int bh = z / 3, mat = z % 3;
    const float* L = ((mat == 2) ? g_k1 : g_qn) + bh * NS * DH;
    const float* R = ((mat == 0) ? g_k1 : g_k2) + bh * NS * DH;
    float* C = ((mat == 0) ? g_e1 : (mat == 1) ? g_e2 : g_e3) + (size_t)bh * NS * NS;
    float scale = (mat == 2) ? 0.125f : 1.f;

    __shared__ float As[16][128];
    __shared__ float Bs[16][64];
    int t = threadIdx.x, tx = t & 15, ty = t >> 4;
    int m0 = blockIdx.y * 128, n0 = blockIdx.x * 64;

    float acc[8][4];
#pragma unroll
    for (int i = 0; i < 8; i++)
#pragma unroll
        for (int j = 0; j < 4; j++) acc[i][j] = 0.f;

    for (int kt = 0; kt < 64; kt += 16) {
#pragma unroll
        for (int q = 0; q < 2; q++) {
            int lin = t + q * 256;
            int m = lin & 127, kq = lin >> 7;
            float4 v = *(const float4*)&L[(m0 + m) * 64 + kt + kq * 4];
            As[kq * 4 + 0][m] = v.x; As[kq * 4 + 1][m] = v.y;
            As[kq * 4 + 2][m] = v.z; As[kq * 4 + 3][m] = v.w;
        }
        {
            int n = t & 63, kq = t >> 6;
            float4 v = *(const float4*)&R[(n0 + n) * 64 + kt + kq * 4];
            Bs[kq * 4 + 0][n] = v.x; Bs[kq * 4 + 1][n] = v.y;
            Bs[kq * 4 + 2][n] = v.z; Bs[kq * 4 + 3][n] = v.w;
        }
        __syncthreads();
#pragma unroll
        for (int kk = 0; kk < 16; kk++) {
            float4 b = *(float4*)&Bs[kk][tx * 4];
            float a[8];
#pragma unroll
            for (int i = 0; i < 8; i++) a[i] = As[kk][ty * 8 + i];
#pragma unroll
            for (int i = 0; i < 8; i++) {
                acc[i][0] += a[i] * b.x; acc[i][1] += a[i] * b.y;
                acc[i][2] += a[i] * b.z; acc[i][3] += a[i] * b.w;
            }
        }
        __syncthreads();
    }
#pragma unroll
    for (int i = 0; i < 8; i++) {
        float4 v;
        v.x = __expf(fminf(40.f, fmaxf(-40.f, acc[i][0] * scale)));
        v.y = __expf(fminf(40.f, fmaxf(-40.f, acc[i][1] * scale)));
        v.z = __expf(fminf(40.f, fmaxf(-40.f, acc[i][2] * scale)));
        v.w = __expf(fminf(40.f, fmaxf(-40.f, acc[i][3] * scale)));
        *(float4*)&C[(size_t)(m0 + ty * 8 + i) * NS + n0 + tx * 4] = v;
    }
}

// ---------------- heavy: mma.sync tf32 + ldmatrix, pipelined frags ----------------
// CTA (dg, ib, jb, bh): tile 64(i) x 128(j), 256 threads, 8 warps,
// warp grid 2(i) x 4(j), warp tile 32x32.
// Mainloop software-pipelines LDSM one k-step ahead (ping-pong fragments)
// so the LDSM latency/issue hides under the tensor pipe.
#define BPCH 260
#define APCH 132
#define B_OFF 0
#define A_OFF 133120
#define RED_OFF 200704
#define V2_OFF 201728
#define SMEM_SZ 202752

// one k-half mainloop with 1-step fragment prefetch
#define HALF_LOOP(AOFS, BOFS)                                                         \
    {                                                                                 \
        uint32_t fa[2][8], fb[2][8];                                                  \
        ldsm_x4(fa[0][0], fa[0][1], fa[0][2], fa[0][3], aBase + (AOFS));              \
        ldsm_x4(fa[0][4], fa[0][5], fa[0][6], fa[0][7], aBase + (AOFS) + 8448);       \
        ldsm_x4(fb[0][0], fb[0][1], fb[0][2], fb[0][3], bBase + (BOFS));              \
        ldsm_x4(fb[0][4], fb[0][5], fb[0][6], fb[0][7], bBase + (BOFS) + 16640);      \
        _Pragma("unroll")                                                             \
        for (int ks = 0; ks < 16; ks++) {                                             \
            const int cur = ks & 1, nxt = cur ^ 1;                                    \
            if (ks < 15) {                                                            \
                uint32_t ko = (uint32_t)((ks + 1) * 32);                              \
                ldsm_x4(fa[nxt][0], fa[nxt][1], fa[nxt][2], fa[nxt][3],               \
                        aBase + (AOFS) + ko);                                         \
                ldsm_x4(fa[nxt][4], fa[nxt][5], fa[nxt][6], fa[nxt][7],               \
                        aBase + (AOFS) + 8448 + ko);                                  \
                ldsm_x4(fb[nxt][0], fb[nxt][1], fb[nxt][2], fb[nxt][3],               \
                        bBase + (BOFS) + ko);                                         \
                ldsm_x4(fb[nxt][4], fb[nxt][5], fb[nxt][6], fb[nxt][7],               \
                        bBase + (BOFS) + 16640 + ko);                                 \
            }                                                                         \
            mma_tf32(acc[0][0], fa[cur][0], fa[cur][1], fa[cur][2], fa[cur][3],       \
                     fb[cur][0], fb[cur][1]);                                         \
            mma_tf32(acc[0][1], fa[cur][0], fa[cur][1], fa[cur][2], fa[cur][3],       \
                     fb[cur][2], fb[cur][3]);                                         \
            mma_tf32(acc[0][2], fa[cur][0], fa[cur][1], fa[cur][2], fa[cur][3],       \
                     fb[cur][4], fb[cur][5]);                                         \
            mma_tf32(acc[0][3], fa[cur][0], fa[cur][1], fa[cur][2], fa[cur][3],       \
                     fb[cur][6], fb[cur][7]);                                         \
            mma_tf32(acc[1][0], fa[cur][4], fa[cur][5], fa[cur][6], fa[cur][7],       \
                     fb[cur][0], fb[cur][1]);                                         \
            mma_tf32(acc[1][1], fa[cur][4], fa[cur][5], fa[cur][6], fa[cur][7],       \
                     fb[cur][2], fb[cur][3]);                                         \
            mma_tf32(acc[1][2], fa[cur][4], fa[cur][5], fa[cur][6], fa[cur][7],       \
                     fb[cur][4], fb[cur][5]);                                         \
            mma_tf32(acc[1][3], fa[cur][4], fa[cur][5], fa[cur][6], fa[cur][7],       \
                     fb[cur][6], fb[cur][7]);                                         \
        }                                                                             \
    }

__global__ void __launch_bounds__(256, 1) heavy_mma() {
    extern __shared__ __align__(16) char smem[];
    const uint32_t sb = smem_u32(smem);
    uint32_t* Bu  = (uint32_t*)(smem + B_OFF);
    uint32_t* Au  = (uint32_t*)(smem + A_OFF);
    float*    red = (float*)(smem + RED_OFF);
    float*    v2s = (float*)(smem + V2_OFF);

    int t = threadIdx.x, lane = t & 31, wid = t >> 5;
    int wi = wid >> 2, wj = wid & 3;            // 2(i) x 4(j)
    int i0 = wi * 32, j0 = wj * 32;
    int dg = blockIdx.x;                        // 0..4, 13 channels each
    int ib = blockIdx.y >> 1, jb = blockIdx.y & 1;
    int bh = blockIdx.z;

    const float* e2p = g_e2 + (size_t)bh * 65536 + (size_t)(ib * 64) * 256;
    const float* e3p = g_e3 + (size_t)bh * 65536 + (size_t)(jb * 128) * 256;
    const float* e1p = g_e1 + (size_t)bh * 65536 + (size_t)(ib * 64) * 256 + jb * 128;
    const float* v1b = g_v1t + (size_t)bh * DH * NS;
    const float* v2b = g_v2t + (size_t)bh * DH * NS;

    // ---- B static: tf32(e3) [128 x 256] pitch 260, built once ----
    for (int idx = t; idx < 8192; idx += 256) {   // 128 rows x 64 float4
        int r = idx >> 6, q = (idx & 63) << 2;
        float4 b = *(const float4*)&e3p[r * 256 + q];
        uint4 u;
        u.x = cvt_tf32(b.x); u.y = cvt_tf32(b.y);
        u.z = cvt_tf32(b.z); u.w = cvt_tf32(b.w);
        *(uint4*)&Bu[r * BPCH + q] = u;
    }

    // ---- raw e2 tile -> registers (once) ----
    float4 st0[8], st1[8];
#pragma unroll
    for (int q = 0; q < 8; q++) {
        int row = wid + 8 * q;
        st0[q] = *(const float4*)&e2p[row * 256 + lane * 4];
        st1[q] = *(const float4*)&e2p[row * 256 + 128 + lane * 4];
    }

    // ---- e1 fragments in registers (d-independent) ----
    float er[2][4][4];
#pragma unroll
    for (int mt = 0; mt < 2; mt++) {
        int ir = i0 + mt * 16 + (lane >> 2);
#pragma unroll
        for (int nt = 0; nt < 4; nt++) {
            int j = j0 + nt * 8 + (lane & 3) * 2;
            float2 w0 = *(const float2*)&e1p[(size_t)ir * 256 + j];
            float2 w1 = *(const float2*)&e1p[(size_t)(ir + 8) * 256 + j];
            er[mt][nt][0] = w0.x; er[mt][nt][1] = w0.y;
            er[mt][nt][2] = w1.x; er[mt][nt][3] = w1.y;
        }
    }

    // ---- v2 smem + v1 regs for channel 0 ----
    int d0 = dg * 13;
    v2s[t] = v2b[(size_t)d0 * NS + t];
    float vr0[4], vr1[4];
#pragma unroll
    for (int nt = 0; nt < 4; nt++) {
        int jg = jb * 128 + j0 + nt * 8 + (lane & 3) * 2;
        vr0[nt] = v1b[(size_t)d0 * NS + jg];
        vr1[nt] = v1b[(size_t)d0 * NS + jg + 1];
    }

    // ---- ldmatrix lane addresses ----
    int lr = lane & 7;
    uint32_t aRow = (uint32_t)(i0 + ((lane >> 3) & 1) * 8 + lr);
    uint32_t aK   = (uint32_t)((lane >> 4) * 4);
    uint32_t aBase = sb + A_OFF + (aRow * APCH + aK) * 4;  // +half*33792 +mt*8448 +ks*32
    uint32_t bRow = (uint32_t)(j0 + ((lane >> 4) & 1) * 8 + lr);
    uint32_t bK   = (uint32_t)(((lane >> 3) & 1) * 4);
    uint32_t bBase = sb + B_OFF + (bRow * BPCH + bK) * 4;  // +ntp*16640 +half*512 +ks*32

    __syncthreads();   // B + v2s ready

    float acc[2][4][4];

#pragma unroll 1
    for (int ch = 0; ch < 13; ch++) {
        int d = dg * 13 + ch;

        // ===== half 0: build A = tf32(e2*v2) into buf0 =====
#pragma unroll
        for (int q = 0; q < 8; q++) {
            int row = wid + 8 * q;
            float4 a = st0[q];
            float4 w = *(const float4*)&v2s[lane * 4];
            uint4 u;
            u.x = cvt_tf32(a.x * w.x); u.y = cvt_tf32(a.y * w.y);
            u.z = cvt_tf32(a.z * w.z); u.w = cvt_tf32(a.w * w.w);
            *(uint4*)&Au[row * APCH + lane * 4] = u;
        }
        __syncthreads();

#pragma unroll
        for (int m = 0; m < 2; m++)
#pragma unroll
            for (int n = 0; n < 4; n++)
#pragma unroll
                for (int c = 0; c < 4; c++) acc[m][n][c] = 0.f;

        HALF_LOOP(0u, 0u)

        // ===== half 1: build A into buf1 =====
#pragma unroll
        for (int q = 0; q < 8; q++) {
            int row = wid + 8 * q;
            float4 a = st1[q];
            float4 w = *(const float4*)&v2s[128 + lane * 4];
            uint4 u;
            u.x = cvt_tf32(a.x * w.x); u.y = cvt_tf32(a.y * w.y);
            u.z = cvt_tf32(a.z * w.z); u.w = cvt_tf32(a.w * w.w);
            *(uint4*)&Au[(64 + row) * APCH + lane * 4] = u;
        }
        __syncthreads();

        HALF_LOOP(33792u, 512u)

        // ===== epilogue: partial[i] = sum_j e1*v1*G =====
#pragma unroll
        for (int mt = 0; mt < 2; mt++) {
            float p0 = 0.f, p1 = 0.f;
#pragma unroll
            for (int nt = 0; nt < 4; nt++) {
                p0 += acc[mt][nt][0] * er[mt][nt][0] * vr0[nt]
                    + acc[mt][nt][1] * er[mt][nt][1] * vr1[nt];
                p1 += acc[mt][nt][2] * er[mt][nt][2] * vr0[nt]
                    + acc[mt][nt][3] * er[mt][nt][3] * vr1[nt];
            }
            p0 += __shfl_xor_sync(0xffffffffu, p0, 1);
            p0 += __shfl_xor_sync(0xffffffffu, p0, 2);
            p1 += __shfl_xor_sync(0xffffffffu, p1, 1);
            p1 += __shfl_xor_sync(0xffffffffu, p1, 2);
            if ((lane & 3) == 0) {
                int il = i0 + mt * 16 + (lane >> 2);
                red[il * 4 + wj] = p0;
                red[(il + 8) * 4 + wj] = p1;
            }
        }
        __syncthreads();

        // final store + stage next channel's v1/v2
        if (t < 64) {
            float s = red[t * 4] + red[t * 4 + 1] + red[t * 4 + 2] + red[t * 4 + 3];
            int ig = ib * 64 + t;
            if (d < 64) g_numP[jb][((size_t)bh * NS + ig) * DH + d] = s;
            else        g_denP[jb][(size_t)bh * NS + ig] = s;
        }
        int d2 = d + 1;
        v2s[t] = (d2 < 64) ? v2b[(size_t)d2 * NS + t] : 1.f;
#pragma unroll
        for (int nt = 0; nt < 4; nt++) {
            int jg = jb * 128 + j0 + nt * 8 + (lane & 3) * 2;
            vr0[nt] = (d2 < 64) ? v1b[(size_t)d2 * NS + jg] : 1.f;
            vr1[nt] = (d2 < 64) ? v1b[(size_t)d2 * NS + jg + 1] : 1.f;
        }
        __syncthreads();
    }
}

// ---------------- normalize: combine 2 jb partials, o = num/den ----------------
__global__ void normalize_kernel() {
    int idx = blockIdx.x * 256 + threadIdx.x;   // 0..262143
    int dd = idx & 63;
    int i  = (idx >> 6) & 255;
    int bh = idx >> 14;
    int b = bh >> 3, h = bh & 7;
    float num = g_numP[0][idx] + g_numP[1][idx];
    float den = g_denP[0][bh * NS + i] + g_denP[1][bh * NS + i];
    g_o[(size_t)(b * 256 + i) * 512 + h * 64 + dd] = num / den;
}

extern "C" void kernel_launch(void* const* d_in, const int* in_sizes, int n_in,
                              void* d_out, int out_size) {
    const float* x     = (const float*)d_in[0];
    const float* w_qkv = (const float*)d_in[1];
    const float* w_out = (const float*)d_in[2];
    const float* qw    = (const float*)d_in[3];
    const float* k1w   = (const float*)d_in[4];
    const float* k2w   = (const float*)d_in[5];
    float* out = (float*)d_out;

    float *qkv_p = nullptr, *o_p = nullptr;
    cudaGetSymbolAddress((void**)&qkv_p, g_qkv);
    cudaGetSymbolAddress((void**)&o_p, g_o);

    cudaFuncSetAttribute(heavy_mma, cudaFuncAttributeMaxDynamicSharedMemorySize, SMEM_SZ);

    // 1) qkv = x @ w_qkv   [512,512]@[512,2560]
    sgemm128x64<<<dim3(40, 4), 256>>>(x, w_qkv, qkv_p, 512, 2560, 512);
    // 2) split + rmsnorm + pack
    pack_norm<<<4096, 64>>>(qw, k1w, k2w);
    // 3) e1/e2/e3
    sims_kernel<<<dim3(4, 2, 48), 256>>>();
    // 4) heavy: 5 dgroups x (ib 4 x jb 2) x bh 16 = 640 CTAs
    heavy_mma<<<dim3(5, 8, 16), 256, SMEM_SZ>>>();
    // 5) normalize (sum 2 jb partials)
    normalize_kernel<<<1024, 256>>>();
    // 6) out = o @ w_out   [512,512]@[512,512]
    sgemm128x64<<<dim3(8, 4), 256>>>(o_p, w_out, out, 512, 512, 512);
}